// round 1
// baseline (speedup 1.0000x reference)
#include <cuda_runtime.h>
#include <math.h>

#define T_TOK 8192
#define D_DIM 1024
#define I_DIM 2816
#define E_NUM 16
#define TOPK  2
#define NSLOT (T_TOK * TOPK)

#define BM 128
#define BN 128
#define BK 16
#define MAX_MT (NSLOT / BM + E_NUM)   // 144 worst-case m-tiles across experts

// ---------------- static device scratch (no allocations allowed) ----------------
__device__ float g_probs[T_TOK * E_NUM];
__device__ int   g_topk_idx[NSLOT];
__device__ float g_topk_w[NSLOT];
__device__ int   g_counts[E_NUM];
__device__ int   g_offsets[E_NUM + 1];
__device__ int   g_cursor[E_NUM];
__device__ int   g_mtile_prefix[E_NUM + 1];
__device__ int   g_slot_token[NSLOT];
__device__ float g_slot_w[NSLOT];
__device__ int   g_slot_of[NSLOT];

__device__ float g_Xg[(size_t)NSLOT * D_DIM];   // gathered tokens   (64 MB)
__device__ float g_H [(size_t)NSLOT * I_DIM];   // Hg then H in-place (180 MB)
__device__ float g_Y [(size_t)NSLOT * D_DIM];   // per-slot outputs  (64 MB)

// ---------------- init: zero expert counts ----------------
__global__ void init_kernel() {
    if (threadIdx.x < E_NUM) g_counts[threadIdx.x] = 0;
}

// ---------------- router: logits, softmax, top-2, counts ----------------
__global__ void router_kernel(const float* __restrict__ x,
                              const float* __restrict__ gw) {
    int t = blockIdx.x;
    const float* xr = x + (size_t)t * D_DIM;
    float acc[E_NUM];
#pragma unroll
    for (int e = 0; e < E_NUM; e++) acc[e] = 0.f;
    for (int d = threadIdx.x; d < D_DIM; d += 256) {
        float xv = xr[d];
        const float* g = gw + d * E_NUM;
#pragma unroll
        for (int e = 0; e < E_NUM; e++) acc[e] = fmaf(xv, g[e], acc[e]);
    }
#pragma unroll
    for (int e = 0; e < E_NUM; e++)
        for (int off = 16; off > 0; off >>= 1)
            acc[e] += __shfl_down_sync(0xffffffffu, acc[e], off);

    __shared__ float wsum[8][E_NUM];
    int warp = threadIdx.x >> 5, lane = threadIdx.x & 31;
    if (lane == 0) {
#pragma unroll
        for (int e = 0; e < E_NUM; e++) wsum[warp][e] = acc[e];
    }
    __syncthreads();

    if (threadIdx.x == 0) {
        float logit[E_NUM];
        for (int e = 0; e < E_NUM; e++) {
            float s = 0.f;
            for (int w = 0; w < 8; w++) s += wsum[w][e];
            logit[e] = s;
        }
        float m = logit[0];
        for (int e = 1; e < E_NUM; e++) m = fmaxf(m, logit[e]);
        float p[E_NUM], sum = 0.f;
        for (int e = 0; e < E_NUM; e++) { p[e] = expf(logit[e] - m); sum += p[e]; }
        float inv = 1.f / sum;
        for (int e = 0; e < E_NUM; e++) { p[e] *= inv; g_probs[t * E_NUM + e] = p[e]; }

        int i0 = 0;
        for (int e = 1; e < E_NUM; e++) if (p[e] > p[i0]) i0 = e;
        int i1 = (i0 == 0) ? 1 : 0;
        for (int e = 0; e < E_NUM; e++) if (e != i0 && p[e] > p[i1]) i1 = e;

        float wn = p[i0] + p[i1];
        g_topk_idx[t * 2 + 0] = i0;
        g_topk_idx[t * 2 + 1] = i1;
        g_topk_w[t * 2 + 0] = p[i0] / wn;
        g_topk_w[t * 2 + 1] = p[i1] / wn;
        atomicAdd(&g_counts[i0], 1);
        atomicAdd(&g_counts[i1], 1);
    }
}

// ---------------- offsets / tile prefix (single thread, 16 iters) ----------------
__global__ void offsets_kernel() {
    if (threadIdx.x == 0) {
        int o = 0, mt = 0;
        g_mtile_prefix[0] = 0;
        for (int e = 0; e < E_NUM; e++) {
            g_offsets[e] = o;
            o += g_counts[e];
            mt += (g_counts[e] + BM - 1) / BM;
            g_mtile_prefix[e + 1] = mt;
            g_cursor[e] = 0;
        }
        g_offsets[E_NUM] = o;
    }
}

// ---------------- scatter slot assignments ----------------
__global__ void scatter_pos_kernel() {
    int idx = blockIdx.x * 256 + threadIdx.x;
    if (idx >= NSLOT) return;
    int e = g_topk_idx[idx];
    int pos = g_offsets[e] + atomicAdd(&g_cursor[e], 1);
    g_slot_token[pos] = idx >> 1;
    g_slot_w[pos]     = g_topk_w[idx];
    g_slot_of[idx]    = pos;
}

// ---------------- gather token rows ----------------
__global__ void gather_kernel(const float* __restrict__ x) {
    int s = blockIdx.x;
    int t = g_slot_token[s];
    const float4* src = (const float4*)(x + (size_t)t * D_DIM);
    float4* dst = (float4*)(g_Xg + (size_t)s * D_DIM);
    dst[threadIdx.x] = src[threadIdx.x];   // 256 threads * float4 = 1024 floats
}

// ---------------- grouped SGEMM (fixed grid, device-side tile decode) ----------------
// MODE 0: C = A @ B[e]                (A=g_Xg, B=Wg, C=g_H)
// MODE 1: C = silu(C) * (A @ B[e])    (A=g_Xg, B=Wu, C=g_H in-place)
// MODE 2: C = (A @ B[e]) * slot_w     (A=g_H,  B=Wd, C=g_Y)
template <int KD, int ND, int MODE>
__global__ __launch_bounds__(256)
void grouped_gemm(const float* __restrict__ Aglob,
                  const float* __restrict__ Bglob,
                  float* __restrict__ Cglob) {
    int mb = blockIdx.x, nb = blockIdx.y;
    if (mb >= g_mtile_prefix[E_NUM]) return;
    int e = 0;
    while (mb >= g_mtile_prefix[e + 1]) e++;
    int m0   = g_offsets[e] + (mb - g_mtile_prefix[e]) * BM;
    int mmax = g_offsets[e + 1];

    const float* A = Aglob;
    const float* B = Bglob + (size_t)e * KD * ND + nb * BN;

    __shared__ float As[BK][BM + 4];
    __shared__ float Bs[BK][BN];

    float acc[8][8];
#pragma unroll
    for (int i = 0; i < 8; i++)
#pragma unroll
        for (int j = 0; j < 8; j++) acc[i][j] = 0.f;

    const int tid = threadIdx.x;
    const int tx = tid & 15, ty = tid >> 4;

    for (int k0 = 0; k0 < KD; k0 += BK) {
#pragma unroll
        for (int rep = 0; rep < 2; rep++) {
            int l = tid + rep * 256;          // 0..511 float4 slots
            int row = l >> 2;
            int kq = (l & 3) << 2;
            int gr = m0 + row;
            float4 v = make_float4(0.f, 0.f, 0.f, 0.f);
            if (gr < mmax)
                v = *(const float4*)(A + (size_t)gr * KD + k0 + kq);
            As[kq + 0][row] = v.x;
            As[kq + 1][row] = v.y;
            As[kq + 2][row] = v.z;
            As[kq + 3][row] = v.w;
        }
#pragma unroll
        for (int rep = 0; rep < 2; rep++) {
            int l = tid + rep * 256;
            int kk = l >> 5;
            int nn = (l & 31) << 2;
            *(float4*)(&Bs[kk][nn]) =
                *(const float4*)(B + (size_t)(k0 + kk) * ND + nn);
        }
        __syncthreads();
#pragma unroll
        for (int kk = 0; kk < BK; kk++) {
            float af[8], bf[8];
            *(float4*)(af)     = *(const float4*)(&As[kk][ty * 8]);
            *(float4*)(af + 4) = *(const float4*)(&As[kk][ty * 8 + 4]);
            *(float4*)(bf)     = *(const float4*)(&Bs[kk][tx * 8]);
            *(float4*)(bf + 4) = *(const float4*)(&Bs[kk][tx * 8 + 4]);
#pragma unroll
            for (int i = 0; i < 8; i++)
#pragma unroll
                for (int j = 0; j < 8; j++)
                    acc[i][j] = fmaf(af[i], bf[j], acc[i][j]);
        }
        __syncthreads();
    }

    int gc = nb * BN + tx * 8;
#pragma unroll
    for (int i = 0; i < 8; i++) {
        int gr = m0 + ty * 8 + i;
        if (gr >= mmax) continue;
        float4* cp = (float4*)(Cglob + (size_t)gr * ND + gc);
        if (MODE == 0) {
            cp[0] = make_float4(acc[i][0], acc[i][1], acc[i][2], acc[i][3]);
            cp[1] = make_float4(acc[i][4], acc[i][5], acc[i][6], acc[i][7]);
        } else if (MODE == 1) {
            float4 h0 = cp[0], h1 = cp[1];
            float hv[8] = {h0.x, h0.y, h0.z, h0.w, h1.x, h1.y, h1.z, h1.w};
            float r[8];
#pragma unroll
            for (int j = 0; j < 8; j++) {
                float s = hv[j] / (1.f + expf(-hv[j]));   // silu
                r[j] = s * acc[i][j];
            }
            cp[0] = make_float4(r[0], r[1], r[2], r[3]);
            cp[1] = make_float4(r[4], r[5], r[6], r[7]);
        } else {
            float w = g_slot_w[gr];
            cp[0] = make_float4(acc[i][0] * w, acc[i][1] * w, acc[i][2] * w, acc[i][3] * w);
            cp[1] = make_float4(acc[i][4] * w, acc[i][5] * w, acc[i][6] * w, acc[i][7] * w);
        }
    }
}

// ---------------- combine: out[t] = Y[slot0] + Y[slot1] (fixed order) ----------------
__global__ void combine_kernel(float* __restrict__ out) {
    int t = blockIdx.x;
    int s0 = g_slot_of[t * 2 + 0];
    int s1 = g_slot_of[t * 2 + 1];
    const float4* y0 = (const float4*)(g_Y + (size_t)s0 * D_DIM);
    const float4* y1 = (const float4*)(g_Y + (size_t)s1 * D_DIM);
    float4 a = y0[threadIdx.x], b = y1[threadIdx.x];
    float4 r = make_float4(a.x + b.x, a.y + b.y, a.z + b.z, a.w + b.w);
    ((float4*)(out + (size_t)t * D_DIM))[threadIdx.x] = r;
}

// ---------------- aux loss (deterministic fixed-order reduction) ----------------
__global__ void aux_kernel(float* __restrict__ out, int out_size) {
    __shared__ float red[256];
    __shared__ float esum[E_NUM];
    float part[E_NUM];
#pragma unroll
    for (int e = 0; e < E_NUM; e++) part[e] = 0.f;
    for (int t = threadIdx.x; t < T_TOK; t += 256) {
#pragma unroll
        for (int e = 0; e < E_NUM; e++) part[e] += g_probs[t * E_NUM + e];
    }
    for (int e = 0; e < E_NUM; e++) {
        red[threadIdx.x] = part[e];
        __syncthreads();
        for (int off = 128; off > 0; off >>= 1) {
            if (threadIdx.x < off) red[threadIdx.x] += red[threadIdx.x + off];
            __syncthreads();
        }
        if (threadIdx.x == 0) esum[e] = red[0];
        __syncthreads();
    }
    if (threadIdx.x == 0) {
        float aux = 0.f;
        for (int e = 0; e < E_NUM; e++) {
            float f = (float)g_counts[e] / (float)T_TOK;     // tokens_per_expert
            float pm = esum[e] / (float)T_TOK;               // mean router prob
            aux += f * pm;
        }
        aux *= 0.01f * (float)E_NUM;
        if (out_size > T_TOK * D_DIM) out[(size_t)T_TOK * D_DIM] = aux;
    }
}

// ---------------- launch ----------------
extern "C" void kernel_launch(void* const* d_in, const int* in_sizes, int n_in,
                              void* d_out, int out_size) {
    const float* x      = (const float*)d_in[0];  // [4,2048,1024]
    const float* gate_w = (const float*)d_in[1];  // [1024,16]
    const float* Wg     = (const float*)d_in[2];  // [16,1024,2816]
    const float* Wu     = (const float*)d_in[3];  // [16,1024,2816]
    const float* Wd     = (const float*)d_in[4];  // [16,2816,1024]
    float* out = (float*)d_out;

    float* dXg; cudaGetSymbolAddress((void**)&dXg, g_Xg);
    float* dH;  cudaGetSymbolAddress((void**)&dH,  g_H);
    float* dY;  cudaGetSymbolAddress((void**)&dY,  g_Y);

    init_kernel<<<1, 32>>>();
    router_kernel<<<T_TOK, 256>>>(x, gate_w);
    offsets_kernel<<<1, 32>>>();
    scatter_pos_kernel<<<(NSLOT + 255) / 256, 256>>>();
    gather_kernel<<<NSLOT, 256>>>(x);

    dim3 g1(MAX_MT, I_DIM / BN);   // 144 x 22
    grouped_gemm<D_DIM, I_DIM, 0><<<g1, 256>>>(dXg, Wg, dH);
    grouped_gemm<D_DIM, I_DIM, 1><<<g1, 256>>>(dXg, Wu, dH);
    dim3 g2(MAX_MT, D_DIM / BN);   // 144 x 8
    grouped_gemm<I_DIM, D_DIM, 2><<<g2, 256>>>(dH, Wd, dY);

    combine_kernel<<<T_TOK, 256>>>(out);
    aux_kernel<<<1, 256>>>(out, out_size);
}

// round 3
// speedup vs baseline: 2.2899x; 2.2899x over previous
#include <cuda_runtime.h>
#include <math.h>
#include <stdint.h>

#define T_TOK 8192
#define D_DIM 1024
#define I_DIM 2816
#define E_NUM 16
#define NSLOT (T_TOK * 2)
#define BM 128
#define BN 64
#define BK 16
#define MAX_MT (NSLOT / BM + E_NUM)   // 144
#define SSTRIDE 20                    // padded k-stride (words) for conflict-free frags

// ================= static device scratch =================
__device__ float g_probs[T_TOK * E_NUM];
__device__ int   g_topk_idx[NSLOT];
__device__ float g_topk_w[NSLOT];
__device__ int   g_counts[E_NUM];
__device__ int   g_offsets[E_NUM + 1];
__device__ int   g_cursor[E_NUM];
__device__ int   g_mtile_prefix[E_NUM + 1];
__device__ int   g_slot_token[NSLOT];
__device__ float g_slot_w[NSLOT];
__device__ int   g_slot_of[NSLOT];

__device__ float g_H[(size_t)NSLOT * I_DIM];   // silu(XWg)*(XWu)
__device__ float g_Y[(size_t)NSLOT * D_DIM];

// ================= helpers =================
__device__ __forceinline__ float f2tf(float f) {
    uint32_t r; asm("cvt.rna.tf32.f32 %0, %1;" : "=r"(r) : "f"(f));
    return __uint_as_float(r);
}

#define MMA_TF32(d, a0, a1, a2, a3, b0, b1) \
    asm volatile( \
        "mma.sync.aligned.m16n8k8.row.col.f32.tf32.tf32.f32 " \
        "{%0,%1,%2,%3}, {%4,%5,%6,%7}, {%8,%9}, {%0,%1,%2,%3};" \
        : "+f"((d)[0]), "+f"((d)[1]), "+f"((d)[2]), "+f"((d)[3]) \
        : "r"(__float_as_uint(a0)), "r"(__float_as_uint(a1)), \
          "r"(__float_as_uint(a2)), "r"(__float_as_uint(a3)), \
          "r"(__float_as_uint(b0)), "r"(__float_as_uint(b1)))

// ================= router pipeline (unchanged from R1, passed) =================
__global__ void init_kernel() {
    if (threadIdx.x < E_NUM) g_counts[threadIdx.x] = 0;
}

__global__ void router_kernel(const float* __restrict__ x, const float* __restrict__ gw) {
    int t = blockIdx.x;
    const float* xr = x + (size_t)t * D_DIM;
    float acc[E_NUM];
#pragma unroll
    for (int e = 0; e < E_NUM; e++) acc[e] = 0.f;
    for (int d = threadIdx.x; d < D_DIM; d += 256) {
        float xv = xr[d];
        const float* g = gw + d * E_NUM;
#pragma unroll
        for (int e = 0; e < E_NUM; e++) acc[e] = fmaf(xv, g[e], acc[e]);
    }
#pragma unroll
    for (int e = 0; e < E_NUM; e++)
        for (int off = 16; off > 0; off >>= 1)
            acc[e] += __shfl_down_sync(0xffffffffu, acc[e], off);
    __shared__ float wsum[8][E_NUM];
    int warp = threadIdx.x >> 5, lane = threadIdx.x & 31;
    if (lane == 0)
#pragma unroll
        for (int e = 0; e < E_NUM; e++) wsum[warp][e] = acc[e];
    __syncthreads();
    if (threadIdx.x == 0) {
        float logit[E_NUM];
        for (int e = 0; e < E_NUM; e++) {
            float s = 0.f;
            for (int w = 0; w < 8; w++) s += wsum[w][e];
            logit[e] = s;
        }
        float m = logit[0];
        for (int e = 1; e < E_NUM; e++) m = fmaxf(m, logit[e]);
        float p[E_NUM], sum = 0.f;
        for (int e = 0; e < E_NUM; e++) { p[e] = expf(logit[e] - m); sum += p[e]; }
        float inv = 1.f / sum;
        for (int e = 0; e < E_NUM; e++) { p[e] *= inv; g_probs[t * E_NUM + e] = p[e]; }
        int i0 = 0;
        for (int e = 1; e < E_NUM; e++) if (p[e] > p[i0]) i0 = e;
        int i1 = (i0 == 0) ? 1 : 0;
        for (int e = 0; e < E_NUM; e++) if (e != i0 && p[e] > p[i1]) i1 = e;
        float wn = p[i0] + p[i1];
        g_topk_idx[t * 2 + 0] = i0;
        g_topk_idx[t * 2 + 1] = i1;
        g_topk_w[t * 2 + 0] = p[i0] / wn;
        g_topk_w[t * 2 + 1] = p[i1] / wn;
        atomicAdd(&g_counts[i0], 1);
        atomicAdd(&g_counts[i1], 1);
    }
}

__global__ void offsets_kernel() {
    if (threadIdx.x == 0) {
        int o = 0, mt = 0;
        g_mtile_prefix[0] = 0;
        for (int e = 0; e < E_NUM; e++) {
            g_offsets[e] = o;
            o += g_counts[e];
            mt += (g_counts[e] + BM - 1) / BM;
            g_mtile_prefix[e + 1] = mt;
            g_cursor[e] = 0;
        }
        g_offsets[E_NUM] = o;
    }
}

__global__ void scatter_pos_kernel() {
    int idx = blockIdx.x * 256 + threadIdx.x;
    if (idx >= NSLOT) return;
    int e = g_topk_idx[idx];
    int pos = g_offsets[e] + atomicAdd(&g_cursor[e], 1);
    g_slot_token[pos] = idx >> 1;
    g_slot_w[pos]     = g_topk_w[idx];
    g_slot_of[idx]    = pos;
}

// ================= FFN1: H = silu(X Wg) * (X Wu)  [mma.sync tf32] =================
__global__ __launch_bounds__(256, 2)
void ffn1_kernel(const float* __restrict__ x,
                 const float* __restrict__ Wg,
                 const float* __restrict__ Wu) {
    __shared__ float As [2][BM * SSTRIDE];
    __shared__ float Bgs[2][BN * SSTRIDE];
    __shared__ float Bus[2][BN * SSTRIDE];

    const int mb = blockIdx.x, nb = blockIdx.y;
    if (mb >= g_mtile_prefix[E_NUM]) return;
    int e = 0;
    while (mb >= g_mtile_prefix[e + 1]) e++;
    const int m0   = g_offsets[e] + (mb - g_mtile_prefix[e]) * BM;
    const int mmax = g_offsets[e + 1];

    const int tid = threadIdx.x, lane = tid & 31, wid = tid >> 5;
    const int wm = wid >> 1;   // 0..3 -> m offset wm*32
    const int wn = wid & 1;    // 0..1 -> n offset wn*32

    // A staging metadata: 512 float4 = 128 rows x 4 k-quads
    int  arow[2], akq[2], atok[2];
    bool av[2];
#pragma unroll
    for (int r = 0; r < 2; r++) {
        int idx = tid + r * 256;
        arow[r] = idx >> 2;
        akq[r]  = (idx & 3) * 4;
        int gr = m0 + arow[r];
        av[r]   = gr < mmax;
        atok[r] = av[r] ? g_slot_token[gr] : 0;
    }
    // B staging: 16k x 64n per matrix; thread -> (n, kq)
    const int bn_ = tid & 63;
    const int bkq = (tid >> 6) * 4;
    const float* bgp = Wg + (size_t)e * D_DIM * I_DIM + (size_t)nb * BN + bn_;
    const float* bup = Wu + (size_t)e * D_DIM * I_DIM + (size_t)nb * BN + bn_;

    float accg[2][4][4], accu[2][4][4];
#pragma unroll
    for (int i = 0; i < 2; i++)
#pragma unroll
        for (int j = 0; j < 4; j++)
#pragma unroll
            for (int k = 0; k < 4; k++) { accg[i][j][k] = 0.f; accu[i][j][k] = 0.f; }

    float4 stA[2];
    float  stBg[4], stBu[4];

    // ---- prologue: load + store tile 0
#pragma unroll
    for (int r = 0; r < 2; r++) {
        stA[r] = make_float4(0.f, 0.f, 0.f, 0.f);
        if (av[r]) stA[r] = *(const float4*)(x + (size_t)atok[r] * D_DIM + akq[r]);
    }
#pragma unroll
    for (int j = 0; j < 4; j++) {
        stBg[j] = bgp[(size_t)(bkq + j) * I_DIM];
        stBu[j] = bup[(size_t)(bkq + j) * I_DIM];
    }
#pragma unroll
    for (int r = 0; r < 2; r++)
        *(float4*)&As[0][arow[r] * SSTRIDE + akq[r]] =
            make_float4(f2tf(stA[r].x), f2tf(stA[r].y), f2tf(stA[r].z), f2tf(stA[r].w));
    *(float4*)&Bgs[0][bn_ * SSTRIDE + bkq] =
        make_float4(f2tf(stBg[0]), f2tf(stBg[1]), f2tf(stBg[2]), f2tf(stBg[3]));
    *(float4*)&Bus[0][bn_ * SSTRIDE + bkq] =
        make_float4(f2tf(stBu[0]), f2tf(stBu[1]), f2tf(stBu[2]), f2tf(stBu[3]));
    __syncthreads();

    const int NC = D_DIM / BK;   // 64
    for (int kc = 0; kc < NC; kc++) {
        const int cur = kc & 1;
        if (kc + 1 < NC) {
            const int k0 = (kc + 1) * BK;
#pragma unroll
            for (int r = 0; r < 2; r++) {
                stA[r] = make_float4(0.f, 0.f, 0.f, 0.f);
                if (av[r]) stA[r] = *(const float4*)(x + (size_t)atok[r] * D_DIM + k0 + akq[r]);
            }
#pragma unroll
            for (int j = 0; j < 4; j++) {
                stBg[j] = bgp[(size_t)(k0 + bkq + j) * I_DIM];
                stBu[j] = bup[(size_t)(k0 + bkq + j) * I_DIM];
            }
        }
        // compute current buffer
#pragma unroll
        for (int ks = 0; ks < 2; ks++) {
            float a[2][4];
#pragma unroll
            for (int mf = 0; mf < 2; mf++) {
                int mrow = wm * 32 + mf * 16 + (lane >> 2);
                int base = mrow * SSTRIDE + ks * 8 + (lane & 3);
                a[mf][0] = As[cur][base];
                a[mf][1] = As[cur][base + 8 * SSTRIDE];
                a[mf][2] = As[cur][base + 4];
                a[mf][3] = As[cur][base + 8 * SSTRIDE + 4];
            }
            float bg[4][2], bu[4][2];
#pragma unroll
            for (int nf = 0; nf < 4; nf++) {
                int nrow = wn * 32 + nf * 8 + (lane >> 2);
                int bb = nrow * SSTRIDE + ks * 8 + (lane & 3);
                bg[nf][0] = Bgs[cur][bb];
                bg[nf][1] = Bgs[cur][bb + 4];
                bu[nf][0] = Bus[cur][bb];
                bu[nf][1] = Bus[cur][bb + 4];
            }
#pragma unroll
            for (int mf = 0; mf < 2; mf++)
#pragma unroll
                for (int nf = 0; nf < 4; nf++) {
                    MMA_TF32(accg[mf][nf], a[mf][0], a[mf][1], a[mf][2], a[mf][3],
                             bg[nf][0], bg[nf][1]);
                    MMA_TF32(accu[mf][nf], a[mf][0], a[mf][1], a[mf][2], a[mf][3],
                             bu[nf][0], bu[nf][1]);
                }
        }
        if (kc + 1 < NC) {
            const int nxt = 1 - cur;
#pragma unroll
            for (int r = 0; r < 2; r++)
                *(float4*)&As[nxt][arow[r] * SSTRIDE + akq[r]] =
                    make_float4(f2tf(stA[r].x), f2tf(stA[r].y), f2tf(stA[r].z), f2tf(stA[r].w));
            *(float4*)&Bgs[nxt][bn_ * SSTRIDE + bkq] =
                make_float4(f2tf(stBg[0]), f2tf(stBg[1]), f2tf(stBg[2]), f2tf(stBg[3]));
            *(float4*)&Bus[nxt][bn_ * SSTRIDE + bkq] =
                make_float4(f2tf(stBu[0]), f2tf(stBu[1]), f2tf(stBu[2]), f2tf(stBu[3]));
        }
        __syncthreads();
    }

    // epilogue: h = silu(g) * u
#pragma unroll
    for (int mf = 0; mf < 2; mf++) {
        int r0 = m0 + wm * 32 + mf * 16 + (lane >> 2);
        int r1 = r0 + 8;
#pragma unroll
        for (int nf = 0; nf < 4; nf++) {
            int col = nb * BN + wn * 32 + nf * 8 + (lane & 3) * 2;
            if (r0 < mmax) {
                float g0 = accg[mf][nf][0], g1 = accg[mf][nf][1];
                float2 o;
                o.x = g0 / (1.f + expf(-g0)) * accu[mf][nf][0];
                o.y = g1 / (1.f + expf(-g1)) * accu[mf][nf][1];
                *(float2*)(g_H + (size_t)r0 * I_DIM + col) = o;
            }
            if (r1 < mmax) {
                float g2 = accg[mf][nf][2], g3 = accg[mf][nf][3];
                float2 o;
                o.x = g2 / (1.f + expf(-g2)) * accu[mf][nf][2];
                o.y = g3 / (1.f + expf(-g3)) * accu[mf][nf][3];
                *(float2*)(g_H + (size_t)r1 * I_DIM + col) = o;
            }
        }
    }
}

// ================= FFN2: Y = (H Wd) * slot_w  [mma.sync tf32] =================
__global__ __launch_bounds__(256, 2)
void ffn2_kernel(const float* __restrict__ Wd) {
    __shared__ float As[2][BM * SSTRIDE];
    __shared__ float Bs[2][BN * SSTRIDE];

    const int mb = blockIdx.x, nb = blockIdx.y;
    if (mb >= g_mtile_prefix[E_NUM]) return;
    int e = 0;
    while (mb >= g_mtile_prefix[e + 1]) e++;
    const int m0   = g_offsets[e] + (mb - g_mtile_prefix[e]) * BM;
    const int mmax = g_offsets[e + 1];

    const int tid = threadIdx.x, lane = tid & 31, wid = tid >> 5;
    const int wm = wid >> 1, wn = wid & 1;

    int  arow[2], akq[2];
    bool av[2];
#pragma unroll
    for (int r = 0; r < 2; r++) {
        int idx = tid + r * 256;
        arow[r] = idx >> 2;
        akq[r]  = (idx & 3) * 4;
        av[r]   = (m0 + arow[r]) < mmax;
    }
    const int bn_ = tid & 63;
    const int bkq = (tid >> 6) * 4;
    const float* bp = Wd + (size_t)e * I_DIM * D_DIM + (size_t)nb * BN + bn_;

    float acc[2][4][4];
#pragma unroll
    for (int i = 0; i < 2; i++)
#pragma unroll
        for (int j = 0; j < 4; j++)
#pragma unroll
            for (int k = 0; k < 4; k++) acc[i][j][k] = 0.f;

    float4 stA[2];
    float  stB[4];

#pragma unroll
    for (int r = 0; r < 2; r++) {
        stA[r] = make_float4(0.f, 0.f, 0.f, 0.f);
        if (av[r]) stA[r] = *(const float4*)(g_H + (size_t)(m0 + arow[r]) * I_DIM + akq[r]);
    }
#pragma unroll
    for (int j = 0; j < 4; j++) stB[j] = bp[(size_t)(bkq + j) * D_DIM];
#pragma unroll
    for (int r = 0; r < 2; r++)
        *(float4*)&As[0][arow[r] * SSTRIDE + akq[r]] =
            make_float4(f2tf(stA[r].x), f2tf(stA[r].y), f2tf(stA[r].z), f2tf(stA[r].w));
    *(float4*)&Bs[0][bn_ * SSTRIDE + bkq] =
        make_float4(f2tf(stB[0]), f2tf(stB[1]), f2tf(stB[2]), f2tf(stB[3]));
    __syncthreads();

    const int NC = I_DIM / BK;   // 176
    for (int kc = 0; kc < NC; kc++) {
        const int cur = kc & 1;
        if (kc + 1 < NC) {
            const int k0 = (kc + 1) * BK;
#pragma unroll
            for (int r = 0; r < 2; r++) {
                stA[r] = make_float4(0.f, 0.f, 0.f, 0.f);
                if (av[r])
                    stA[r] = *(const float4*)(g_H + (size_t)(m0 + arow[r]) * I_DIM + k0 + akq[r]);
            }
#pragma unroll
            for (int j = 0; j < 4; j++) stB[j] = bp[(size_t)(k0 + bkq + j) * D_DIM];
        }
#pragma unroll
        for (int ks = 0; ks < 2; ks++) {
            float a[2][4];
#pragma unroll
            for (int mf = 0; mf < 2; mf++) {
                int mrow = wm * 32 + mf * 16 + (lane >> 2);
                int base = mrow * SSTRIDE + ks * 8 + (lane & 3);
                a[mf][0] = As[cur][base];
                a[mf][1] = As[cur][base + 8 * SSTRIDE];
                a[mf][2] = As[cur][base + 4];
                a[mf][3] = As[cur][base + 8 * SSTRIDE + 4];
            }
            float b[4][2];
#pragma unroll
            for (int nf = 0; nf < 4; nf++) {
                int nrow = wn * 32 + nf * 8 + (lane >> 2);
                int bb = nrow * SSTRIDE + ks * 8 + (lane & 3);
                b[nf][0] = Bs[cur][bb];
                b[nf][1] = Bs[cur][bb + 4];
            }
#pragma unroll
            for (int mf = 0; mf < 2; mf++)
#pragma unroll
                for (int nf = 0; nf < 4; nf++)
                    MMA_TF32(acc[mf][nf], a[mf][0], a[mf][1], a[mf][2], a[mf][3],
                             b[nf][0], b[nf][1]);
        }
        if (kc + 1 < NC) {
            const int nxt = 1 - cur;
#pragma unroll
            for (int r = 0; r < 2; r++)
                *(float4*)&As[nxt][arow[r] * SSTRIDE + akq[r]] =
                    make_float4(f2tf(stA[r].x), f2tf(stA[r].y), f2tf(stA[r].z), f2tf(stA[r].w));
            *(float4*)&Bs[nxt][bn_ * SSTRIDE + bkq] =
                make_float4(f2tf(stB[0]), f2tf(stB[1]), f2tf(stB[2]), f2tf(stB[3]));
        }
        __syncthreads();
    }

#pragma unroll
    for (int mf = 0; mf < 2; mf++) {
        int r0 = m0 + wm * 32 + mf * 16 + (lane >> 2);
        int r1 = r0 + 8;
        float w0 = (r0 < mmax) ? g_slot_w[r0] : 0.f;
        float w1 = (r1 < mmax) ? g_slot_w[r1] : 0.f;
#pragma unroll
        for (int nf = 0; nf < 4; nf++) {
            int col = nb * BN + wn * 32 + nf * 8 + (lane & 3) * 2;
            if (r0 < mmax) {
                float2 o = make_float2(acc[mf][nf][0] * w0, acc[mf][nf][1] * w0);
                *(float2*)(g_Y + (size_t)r0 * D_DIM + col) = o;
            }
            if (r1 < mmax) {
                float2 o = make_float2(acc[mf][nf][2] * w1, acc[mf][nf][3] * w1);
                *(float2*)(g_Y + (size_t)r1 * D_DIM + col) = o;
            }
        }
    }
}

// ================= combine + aux (unchanged) =================
__global__ void combine_kernel(float* __restrict__ out) {
    int t = blockIdx.x;
    int s0 = g_slot_of[t * 2 + 0];
    int s1 = g_slot_of[t * 2 + 1];
    const float4* y0 = (const float4*)(g_Y + (size_t)s0 * D_DIM);
    const float4* y1 = (const float4*)(g_Y + (size_t)s1 * D_DIM);
    float4 a = y0[threadIdx.x], b = y1[threadIdx.x];
    ((float4*)(out + (size_t)t * D_DIM))[threadIdx.x] =
        make_float4(a.x + b.x, a.y + b.y, a.z + b.z, a.w + b.w);
}

__global__ void aux_kernel(float* __restrict__ out, int out_size) {
    __shared__ float red[256];
    __shared__ float esum[E_NUM];
    float part[E_NUM];
#pragma unroll
    for (int e = 0; e < E_NUM; e++) part[e] = 0.f;
    for (int t = threadIdx.x; t < T_TOK; t += 256)
#pragma unroll
        for (int e = 0; e < E_NUM; e++) part[e] += g_probs[t * E_NUM + e];
    for (int e = 0; e < E_NUM; e++) {
        red[threadIdx.x] = part[e];
        __syncthreads();
        for (int off = 128; off > 0; off >>= 1) {
            if (threadIdx.x < off) red[threadIdx.x] += red[threadIdx.x + off];
            __syncthreads();
        }
        if (threadIdx.x == 0) esum[e] = red[0];
        __syncthreads();
    }
    if (threadIdx.x == 0) {
        float aux = 0.f;
        for (int e = 0; e < E_NUM; e++)
            aux += ((float)g_counts[e] / (float)T_TOK) * (esum[e] / (float)T_TOK);
        aux *= 0.01f * (float)E_NUM;
        if (out_size > T_TOK * D_DIM) out[(size_t)T_TOK * D_DIM] = aux;
    }
}

// ================= launch =================
extern "C" void kernel_launch(void* const* d_in, const int* in_sizes, int n_in,
                              void* d_out, int out_size) {
    const float* x      = (const float*)d_in[0];
    const float* gate_w = (const float*)d_in[1];
    const float* Wg     = (const float*)d_in[2];
    const float* Wu     = (const float*)d_in[3];
    const float* Wd     = (const float*)d_in[4];
    float* out = (float*)d_out;

    init_kernel<<<1, 32>>>();
    router_kernel<<<T_TOK, 256>>>(x, gate_w);
    offsets_kernel<<<1, 32>>>();
    scatter_pos_kernel<<<(NSLOT + 255) / 256, 256>>>();

    dim3 g1(MAX_MT, I_DIM / BN);   // 144 x 44
    ffn1_kernel<<<g1, 256>>>(x, Wg, Wu);
    dim3 g2(MAX_MT, D_DIM / BN);   // 144 x 16
    ffn2_kernel<<<g2, 256>>>(Wd);

    combine_kernel<<<T_TOK, 256>>>(out);
    aux_kernel<<<1, 256>>>(out, out_size);
}

// round 4
// speedup vs baseline: 2.3264x; 1.0159x over previous
#include <cuda_runtime.h>
#include <math.h>
#include <stdint.h>

#define T_TOK 8192
#define D_DIM 1024
#define I_DIM 2816
#define E_NUM 16
#define NSLOT (T_TOK * 2)
#define BM 128
#define BN 64
#define BK 16
#define MAX_MT (NSLOT / BM + E_NUM)   // 144

// ================= static device scratch =================
__device__ float g_probs[T_TOK * E_NUM];
__device__ int   g_topk_idx[NSLOT];
__device__ float g_topk_w[NSLOT];
__device__ int   g_counts[E_NUM];
__device__ int   g_offsets[E_NUM + 1];
__device__ int   g_cursor[E_NUM];
__device__ int   g_mtile_prefix[E_NUM + 1];
__device__ int   g_slot_token[NSLOT];
__device__ float g_slot_w[NSLOT];
__device__ int   g_slot_of[NSLOT];

__device__ float g_H[(size_t)NSLOT * I_DIM];
__device__ float g_Y[(size_t)NSLOT * D_DIM];

// ================= helpers =================
__device__ __forceinline__ float f2tf(float f) {
    uint32_t r; asm("cvt.rna.tf32.f32 %0, %1;" : "=r"(r) : "f"(f));
    return __uint_as_float(r);
}

#define MMA_TF32(d, a0, a1, a2, a3, b0, b1) \
    asm volatile( \
        "mma.sync.aligned.m16n8k8.row.col.f32.tf32.tf32.f32 " \
        "{%0,%1,%2,%3}, {%4,%5,%6,%7}, {%8,%9}, {%0,%1,%2,%3};" \
        : "+f"((d)[0]), "+f"((d)[1]), "+f"((d)[2]), "+f"((d)[3]) \
        : "r"(__float_as_uint(a0)), "r"(__float_as_uint(a1)), \
          "r"(__float_as_uint(a2)), "r"(__float_as_uint(a3)), \
          "r"(__float_as_uint(b0)), "r"(__float_as_uint(b1)))

// ================= router pipeline (unchanged, validated) =================
__global__ void init_kernel() {
    if (threadIdx.x < E_NUM) g_counts[threadIdx.x] = 0;
}

__global__ void router_kernel(const float* __restrict__ x, const float* __restrict__ gw) {
    int t = blockIdx.x;
    const float* xr = x + (size_t)t * D_DIM;
    float acc[E_NUM];
#pragma unroll
    for (int e = 0; e < E_NUM; e++) acc[e] = 0.f;
    for (int d = threadIdx.x; d < D_DIM; d += 256) {
        float xv = xr[d];
        const float* g = gw + d * E_NUM;
#pragma unroll
        for (int e = 0; e < E_NUM; e++) acc[e] = fmaf(xv, g[e], acc[e]);
    }
#pragma unroll
    for (int e = 0; e < E_NUM; e++)
        for (int off = 16; off > 0; off >>= 1)
            acc[e] += __shfl_down_sync(0xffffffffu, acc[e], off);
    __shared__ float wsum[8][E_NUM];
    int warp = threadIdx.x >> 5, lane = threadIdx.x & 31;
    if (lane == 0)
#pragma unroll
        for (int e = 0; e < E_NUM; e++) wsum[warp][e] = acc[e];
    __syncthreads();
    if (threadIdx.x == 0) {
        float logit[E_NUM];
        for (int e = 0; e < E_NUM; e++) {
            float s = 0.f;
            for (int w = 0; w < 8; w++) s += wsum[w][e];
            logit[e] = s;
        }
        float m = logit[0];
        for (int e = 1; e < E_NUM; e++) m = fmaxf(m, logit[e]);
        float p[E_NUM], sum = 0.f;
        for (int e = 0; e < E_NUM; e++) { p[e] = expf(logit[e] - m); sum += p[e]; }
        float inv = 1.f / sum;
        for (int e = 0; e < E_NUM; e++) { p[e] *= inv; g_probs[t * E_NUM + e] = p[e]; }
        int i0 = 0;
        for (int e = 1; e < E_NUM; e++) if (p[e] > p[i0]) i0 = e;
        int i1 = (i0 == 0) ? 1 : 0;
        for (int e = 0; e < E_NUM; e++) if (e != i0 && p[e] > p[i1]) i1 = e;
        float wn = p[i0] + p[i1];
        g_topk_idx[t * 2 + 0] = i0;
        g_topk_idx[t * 2 + 1] = i1;
        g_topk_w[t * 2 + 0] = p[i0] / wn;
        g_topk_w[t * 2 + 1] = p[i1] / wn;
        atomicAdd(&g_counts[i0], 1);
        atomicAdd(&g_counts[i1], 1);
    }
}

__global__ void offsets_kernel() {
    if (threadIdx.x == 0) {
        int o = 0, mt = 0;
        g_mtile_prefix[0] = 0;
        for (int e = 0; e < E_NUM; e++) {
            g_offsets[e] = o;
            o += g_counts[e];
            mt += (g_counts[e] + BM - 1) / BM;
            g_mtile_prefix[e + 1] = mt;
            g_cursor[e] = 0;
        }
        g_offsets[E_NUM] = o;
    }
}

__global__ void scatter_pos_kernel() {
    int idx = blockIdx.x * 256 + threadIdx.x;
    if (idx >= NSLOT) return;
    int e = g_topk_idx[idx];
    int pos = g_offsets[e] + atomicAdd(&g_cursor[e], 1);
    g_slot_token[pos] = idx >> 1;
    g_slot_w[pos]     = g_topk_w[idx];
    g_slot_of[idx]    = pos;
}

// =====================================================================
// SMEM layout for both FFN kernels:
//   tile row r (m or n), 16 k-values stored permuted: value k goes to
//   word  r*16 + ( (sigma(k) & 3) | ((sigma(k)>>2 ^ (r&3)) << 2) )
//   where sigma(k) = (k&3)*4 + (k>>2).
//   => a thread's fragment k in {c, c+4, c+8, c+12} is one aligned float4
//   at word r*16 + ((c ^ (r&3)) << 2); element i of that float4 is k=c+4i.
// =====================================================================

// ================= FFN1: H = silu(X Wg) * (X Wu) =================
__global__ __launch_bounds__(128, 2)
void ffn1_kernel(const float* __restrict__ x,
                 const float* __restrict__ Wg,
                 const float* __restrict__ Wu) {
    __shared__ __align__(16) float As [2][BM * 16];
    __shared__ __align__(16) float Bgs[2][BN * 16];
    __shared__ __align__(16) float Bus[2][BN * 16];

    const int mb = blockIdx.x, nb = blockIdx.y;
    if (mb >= g_mtile_prefix[E_NUM]) return;
    int e = 0;
    while (mb >= g_mtile_prefix[e + 1]) e++;
    const int m0   = g_offsets[e] + (mb - g_mtile_prefix[e]) * BM;
    const int mmax = g_offsets[e + 1];

    const int tid = threadIdx.x, lane = tid & 31, wid = tid >> 5;
    const int wm = wid >> 1;            // 0..1 -> m offset wm*64
    const int wn = wid & 1;             // 0..1 -> n offset wn*32

    // ---- A staging: thread = (q = k-quad 0..3, rbase), rows rbase+32*rr
    const int q = tid & 3;
    const int rbase = tid >> 2;         // 0..31
    int  arow[4], atok[4];
    bool av[4];
#pragma unroll
    for (int rr = 0; rr < 4; rr++) {
        arow[rr] = rbase + 32 * rr;
        int gr = m0 + arow[rr];
        av[rr]   = gr < mmax;
        atok[rr] = av[rr] ? g_slot_token[gr] : 0;
    }
    // ---- B staging: thread = (c = q, n = rbase + 32*g)
    const float* bgp = Wg + (size_t)e * D_DIM * I_DIM + (size_t)nb * BN;
    const float* bup = Wu + (size_t)e * D_DIM * I_DIM + (size_t)nb * BN;

    float accg[4][4][4], accu[4][4][4];
#pragma unroll
    for (int i = 0; i < 4; i++)
#pragma unroll
        for (int j = 0; j < 4; j++)
#pragma unroll
            for (int k = 0; k < 4; k++) { accg[i][j][k] = 0.f; accu[i][j][k] = 0.f; }

    float4 stA[4];
    float4 stBg[2], stBu[2];

    // ---------------- staging helpers (macro-expanded inline) ----------------
#define FFN1_PREFETCH(K0)                                                        \
    do {                                                                         \
        _Pragma("unroll")                                                        \
        for (int rr = 0; rr < 4; rr++) {                                         \
            stA[rr] = make_float4(0.f, 0.f, 0.f, 0.f);                           \
            if (av[rr])                                                          \
                stA[rr] = *(const float4*)(x + (size_t)atok[rr] * D_DIM + (K0) + 4 * q); \
        }                                                                        \
        _Pragma("unroll")                                                        \
        for (int g = 0; g < 2; g++) {                                            \
            int n = rbase + 32 * g;                                              \
            const float* pg = bgp + (size_t)((K0) + q) * I_DIM + n;              \
            const float* pu = bup + (size_t)((K0) + q) * I_DIM + n;              \
            stBg[g] = make_float4(pg[0], pg[(size_t)4 * I_DIM],                  \
                                  pg[(size_t)8 * I_DIM], pg[(size_t)12 * I_DIM]);\
            stBu[g] = make_float4(pu[0], pu[(size_t)4 * I_DIM],                  \
                                  pu[(size_t)8 * I_DIM], pu[(size_t)12 * I_DIM]);\
        }                                                                        \
    } while (0)

#define FFN1_COMMIT(BUF)                                                         \
    do {                                                                         \
        _Pragma("unroll")                                                        \
        for (int rr = 0; rr < 4; rr++) {                                         \
            int ro = arow[rr] * 16, sw = arow[rr] & 3;                           \
            As[BUF][ro + (((0 ^ sw) << 2) | q)] = f2tf(stA[rr].x);               \
            As[BUF][ro + (((1 ^ sw) << 2) | q)] = f2tf(stA[rr].y);               \
            As[BUF][ro + (((2 ^ sw) << 2) | q)] = f2tf(stA[rr].z);               \
            As[BUF][ro + (((3 ^ sw) << 2) | q)] = f2tf(stA[rr].w);               \
        }                                                                        \
        _Pragma("unroll")                                                        \
        for (int g = 0; g < 2; g++) {                                            \
            int n = rbase + 32 * g;                                              \
            int off = n * 16 + ((q ^ (n & 3)) << 2);                             \
            *(float4*)&Bgs[BUF][off] = make_float4(f2tf(stBg[g].x), f2tf(stBg[g].y), \
                                                   f2tf(stBg[g].z), f2tf(stBg[g].w)); \
            *(float4*)&Bus[BUF][off] = make_float4(f2tf(stBu[g].x), f2tf(stBu[g].y), \
                                                   f2tf(stBu[g].z), f2tf(stBu[g].w)); \
        }                                                                        \
    } while (0)

    FFN1_PREFETCH(0);
    FFN1_COMMIT(0);
    __syncthreads();

    const int c = lane & 3;
    const int lrow = lane >> 2;
    const int NC = D_DIM / BK;          // 64
    for (int kc = 0; kc < NC; kc++) {
        const int cur = kc & 1;
        if (kc + 1 < NC) FFN1_PREFETCH((kc + 1) * BK);

        // fragment loads: one float4 per (row-of-16, c)
        float4 a0[4], a8[4], bg[4], bu[4];
#pragma unroll
        for (int mf = 0; mf < 4; mf++) {
            int r = wm * 64 + mf * 16 + lrow;
            int sw = (c ^ (r & 3)) << 2;
            a0[mf] = *(const float4*)&As[cur][r * 16 + sw];
            a8[mf] = *(const float4*)&As[cur][(r + 8) * 16 + sw];
        }
#pragma unroll
        for (int nf = 0; nf < 4; nf++) {
            int n = wn * 32 + nf * 8 + lrow;
            int off = n * 16 + ((c ^ (n & 3)) << 2);
            bg[nf] = *(const float4*)&Bgs[cur][off];
            bu[nf] = *(const float4*)&Bus[cur][off];
        }
#pragma unroll
        for (int mf = 0; mf < 4; mf++)
#pragma unroll
            for (int nf = 0; nf < 4; nf++) {
                MMA_TF32(accg[mf][nf], a0[mf].x, a8[mf].x, a0[mf].y, a8[mf].y,
                         bg[nf].x, bg[nf].y);
                MMA_TF32(accg[mf][nf], a0[mf].z, a8[mf].z, a0[mf].w, a8[mf].w,
                         bg[nf].z, bg[nf].w);
                MMA_TF32(accu[mf][nf], a0[mf].x, a8[mf].x, a0[mf].y, a8[mf].y,
                         bu[nf].x, bu[nf].y);
                MMA_TF32(accu[mf][nf], a0[mf].z, a8[mf].z, a0[mf].w, a8[mf].w,
                         bu[nf].z, bu[nf].w);
            }

        if (kc + 1 < NC) FFN1_COMMIT(cur ^ 1);
        __syncthreads();
    }

    // epilogue: h = silu(g) * u
#pragma unroll
    for (int mf = 0; mf < 4; mf++) {
        int r0 = m0 + wm * 64 + mf * 16 + lrow;
        int r1 = r0 + 8;
#pragma unroll
        for (int nf = 0; nf < 4; nf++) {
            int col = nb * BN + wn * 32 + nf * 8 + c * 2;
            if (r0 < mmax) {
                float g0 = accg[mf][nf][0], g1 = accg[mf][nf][1];
                float2 o;
                o.x = g0 / (1.f + expf(-g0)) * accu[mf][nf][0];
                o.y = g1 / (1.f + expf(-g1)) * accu[mf][nf][1];
                *(float2*)(g_H + (size_t)r0 * I_DIM + col) = o;
            }
            if (r1 < mmax) {
                float g2 = accg[mf][nf][2], g3 = accg[mf][nf][3];
                float2 o;
                o.x = g2 / (1.f + expf(-g2)) * accu[mf][nf][2];
                o.y = g3 / (1.f + expf(-g3)) * accu[mf][nf][3];
                *(float2*)(g_H + (size_t)r1 * I_DIM + col) = o;
            }
        }
    }
}

// ================= FFN2: Y = (H Wd) * slot_w =================
__global__ __launch_bounds__(128, 2)
void ffn2_kernel(const float* __restrict__ Wd) {
    __shared__ __align__(16) float As[2][BM * 16];
    __shared__ __align__(16) float Bs[2][BN * 16];

    const int mb = blockIdx.x, nb = blockIdx.y;
    if (mb >= g_mtile_prefix[E_NUM]) return;
    int e = 0;
    while (mb >= g_mtile_prefix[e + 1]) e++;
    const int m0   = g_offsets[e] + (mb - g_mtile_prefix[e]) * BM;
    const int mmax = g_offsets[e + 1];

    const int tid = threadIdx.x, lane = tid & 31, wid = tid >> 5;
    const int wm = wid >> 1, wn = wid & 1;

    const int q = tid & 3;
    const int rbase = tid >> 2;
    int  arow[4];
    bool av[4];
#pragma unroll
    for (int rr = 0; rr < 4; rr++) {
        arow[rr] = rbase + 32 * rr;
        av[rr]   = (m0 + arow[rr]) < mmax;
    }
    const float* bp = Wd + (size_t)e * I_DIM * D_DIM + (size_t)nb * BN;

    float acc[4][4][4];
#pragma unroll
    for (int i = 0; i < 4; i++)
#pragma unroll
        for (int j = 0; j < 4; j++)
#pragma unroll
            for (int k = 0; k < 4; k++) acc[i][j][k] = 0.f;

    float4 stA[4];
    float4 stB[2];

#define FFN2_PREFETCH(K0)                                                        \
    do {                                                                         \
        _Pragma("unroll")                                                        \
        for (int rr = 0; rr < 4; rr++) {                                         \
            stA[rr] = make_float4(0.f, 0.f, 0.f, 0.f);                           \
            if (av[rr])                                                          \
                stA[rr] = *(const float4*)(g_H + (size_t)(m0 + arow[rr]) * I_DIM + (K0) + 4 * q); \
        }                                                                        \
        _Pragma("unroll")                                                        \
        for (int g = 0; g < 2; g++) {                                            \
            int n = rbase + 32 * g;                                              \
            const float* p = bp + (size_t)((K0) + q) * D_DIM + n;                \
            stB[g] = make_float4(p[0], p[(size_t)4 * D_DIM],                     \
                                 p[(size_t)8 * D_DIM], p[(size_t)12 * D_DIM]);   \
        }                                                                        \
    } while (0)

#define FFN2_COMMIT(BUF)                                                         \
    do {                                                                         \
        _Pragma("unroll")                                                        \
        for (int rr = 0; rr < 4; rr++) {                                         \
            int ro = arow[rr] * 16, sw = arow[rr] & 3;                           \
            As[BUF][ro + (((0 ^ sw) << 2) | q)] = f2tf(stA[rr].x);               \
            As[BUF][ro + (((1 ^ sw) << 2) | q)] = f2tf(stA[rr].y);               \
            As[BUF][ro + (((2 ^ sw) << 2) | q)] = f2tf(stA[rr].z);               \
            As[BUF][ro + (((3 ^ sw) << 2) | q)] = f2tf(stA[rr].w);               \
        }                                                                        \
        _Pragma("unroll")                                                        \
        for (int g = 0; g < 2; g++) {                                            \
            int n = rbase + 32 * g;                                              \
            int off = n * 16 + ((q ^ (n & 3)) << 2);                             \
            *(float4*)&Bs[BUF][off] = make_float4(f2tf(stB[g].x), f2tf(stB[g].y),\
                                                  f2tf(stB[g].z), f2tf(stB[g].w));\
        }                                                                        \
    } while (0)

    FFN2_PREFETCH(0);
    FFN2_COMMIT(0);
    __syncthreads();

    const int c = lane & 3;
    const int lrow = lane >> 2;
    const int NC = I_DIM / BK;          // 176
    for (int kc = 0; kc < NC; kc++) {
        const int cur = kc & 1;
        if (kc + 1 < NC) FFN2_PREFETCH((kc + 1) * BK);

        float4 a0[4], a8[4], b[4];
#pragma unroll
        for (int mf = 0; mf < 4; mf++) {
            int r = wm * 64 + mf * 16 + lrow;
            int sw = (c ^ (r & 3)) << 2;
            a0[mf] = *(const float4*)&As[cur][r * 16 + sw];
            a8[mf] = *(const float4*)&As[cur][(r + 8) * 16 + sw];
        }
#pragma unroll
        for (int nf = 0; nf < 4; nf++) {
            int n = wn * 32 + nf * 8 + lrow;
            b[nf] = *(const float4*)&Bs[cur][n * 16 + ((c ^ (n & 3)) << 2)];
        }
#pragma unroll
        for (int mf = 0; mf < 4; mf++)
#pragma unroll
            for (int nf = 0; nf < 4; nf++) {
                MMA_TF32(acc[mf][nf], a0[mf].x, a8[mf].x, a0[mf].y, a8[mf].y,
                         b[nf].x, b[nf].y);
                MMA_TF32(acc[mf][nf], a0[mf].z, a8[mf].z, a0[mf].w, a8[mf].w,
                         b[nf].z, b[nf].w);
            }

        if (kc + 1 < NC) FFN2_COMMIT(cur ^ 1);
        __syncthreads();
    }

#pragma unroll
    for (int mf = 0; mf < 4; mf++) {
        int r0 = m0 + wm * 64 + mf * 16 + lrow;
        int r1 = r0 + 8;
        float w0 = (r0 < mmax) ? g_slot_w[r0] : 0.f;
        float w1 = (r1 < mmax) ? g_slot_w[r1] : 0.f;
#pragma unroll
        for (int nf = 0; nf < 4; nf++) {
            int col = nb * BN + wn * 32 + nf * 8 + c * 2;
            if (r0 < mmax)
                *(float2*)(g_Y + (size_t)r0 * D_DIM + col) =
                    make_float2(acc[mf][nf][0] * w0, acc[mf][nf][1] * w0);
            if (r1 < mmax)
                *(float2*)(g_Y + (size_t)r1 * D_DIM + col) =
                    make_float2(acc[mf][nf][2] * w1, acc[mf][nf][3] * w1);
        }
    }
}

// ================= combine + aux (unchanged) =================
__global__ void combine_kernel(float* __restrict__ out) {
    int t = blockIdx.x;
    int s0 = g_slot_of[t * 2 + 0];
    int s1 = g_slot_of[t * 2 + 1];
    const float4* y0 = (const float4*)(g_Y + (size_t)s0 * D_DIM);
    const float4* y1 = (const float4*)(g_Y + (size_t)s1 * D_DIM);
    float4 a = y0[threadIdx.x], b = y1[threadIdx.x];
    ((float4*)(out + (size_t)t * D_DIM))[threadIdx.x] =
        make_float4(a.x + b.x, a.y + b.y, a.z + b.z, a.w + b.w);
}

__global__ void aux_kernel(float* __restrict__ out, int out_size) {
    __shared__ float red[256];
    __shared__ float esum[E_NUM];
    float part[E_NUM];
#pragma unroll
    for (int e = 0; e < E_NUM; e++) part[e] = 0.f;
    for (int t = threadIdx.x; t < T_TOK; t += 256)
#pragma unroll
        for (int e = 0; e < E_NUM; e++) part[e] += g_probs[t * E_NUM + e];
    for (int e = 0; e < E_NUM; e++) {
        red[threadIdx.x] = part[e];
        __syncthreads();
        for (int off = 128; off > 0; off >>= 1) {
            if (threadIdx.x < off) red[threadIdx.x] += red[threadIdx.x + off];
            __syncthreads();
        }
        if (threadIdx.x == 0) esum[e] = red[0];
        __syncthreads();
    }
    if (threadIdx.x == 0) {
        float aux = 0.f;
        for (int e = 0; e < E_NUM; e++)
            aux += ((float)g_counts[e] / (float)T_TOK) * (esum[e] / (float)T_TOK);
        aux *= 0.01f * (float)E_NUM;
        if (out_size > T_TOK * D_DIM) out[(size_t)T_TOK * D_DIM] = aux;
    }
}

// ================= launch =================
extern "C" void kernel_launch(void* const* d_in, const int* in_sizes, int n_in,
                              void* d_out, int out_size) {
    const float* x      = (const float*)d_in[0];
    const float* gate_w = (const float*)d_in[1];
    const float* Wg     = (const float*)d_in[2];
    const float* Wu     = (const float*)d_in[3];
    const float* Wd     = (const float*)d_in[4];
    float* out = (float*)d_out;

    init_kernel<<<1, 32>>>();
    router_kernel<<<T_TOK, 256>>>(x, gate_w);
    offsets_kernel<<<1, 32>>>();
    scatter_pos_kernel<<<(NSLOT + 255) / 256, 256>>>();

    dim3 g1(MAX_MT, I_DIM / BN);   // 144 x 44
    ffn1_kernel<<<g1, 128>>>(x, Wg, Wu);
    dim3 g2(MAX_MT, D_DIM / BN);   // 144 x 16
    ffn2_kernel<<<g2, 128>>>(Wd);

    combine_kernel<<<T_TOK, 256>>>(out);
    aux_kernel<<<1, 256>>>(out, out_size);
}

// round 6
// speedup vs baseline: 2.7162x; 1.1676x over previous
#include <cuda_runtime.h>
#include <cuda_fp16.h>
#include <math.h>
#include <stdint.h>

#define T_TOK 8192
#define D_DIM 1024
#define I_DIM 2816
#define E_NUM 16
#define NSLOT (T_TOK * 2)
#define BM 128
#define BN 64
#define BK 16
#define MAX_MT (NSLOT / BM + E_NUM)   // 144

// pair-permutation: pair p (=k/2) stored at word sigma(p) within an 8-word row
#define SIG(p) (((((p) & 3) << 1)) | ((p) >> 2))

// ================= static device scratch =================
__device__ float    g_probs[T_TOK * E_NUM];
__device__ int      g_topk_idx[NSLOT];
__device__ float    g_topk_w[NSLOT];
__device__ int      g_counts[E_NUM];
__device__ int      g_offsets[E_NUM + 1];
__device__ int      g_cursor[E_NUM];
__device__ int      g_mtile_prefix[E_NUM + 1];
__device__ int      g_slot_token[NSLOT];
__device__ float    g_slot_w[NSLOT];
__device__ int      g_slot_of[NSLOT];

__device__ uint16_t g_H[(size_t)NSLOT * I_DIM];   // fp16 bits (92 MB)
__device__ float    g_Y[(size_t)NSLOT * D_DIM];

// ================= helpers =================
__device__ __forceinline__ uint32_t pack_half2(float a, float b) {
    uint32_t r;
    asm("{ .reg .f16 lo, hi;\n\t"
        "cvt.rn.f16.f32 lo, %1;\n\t"
        "cvt.rn.f16.f32 hi, %2;\n\t"
        "mov.b32 %0, {lo, hi}; }"
        : "=r"(r) : "f"(a), "f"(b));
    return r;
}

#define MMA_F16(d, a0, a1, a2, a3, b0, b1) \
    asm volatile( \
        "mma.sync.aligned.m16n8k16.row.col.f32.f16.f16.f32 " \
        "{%0,%1,%2,%3}, {%4,%5,%6,%7}, {%8,%9}, {%0,%1,%2,%3};" \
        : "+f"((d)[0]), "+f"((d)[1]), "+f"((d)[2]), "+f"((d)[3]) \
        : "r"(a0), "r"(a1), "r"(a2), "r"(a3), "r"(b0), "r"(b1))

// ================= router pipeline (unchanged, validated) =================
__global__ void init_kernel() {
    if (threadIdx.x < E_NUM) g_counts[threadIdx.x] = 0;
}

__global__ void router_kernel(const float* __restrict__ x, const float* __restrict__ gw) {
    int t = blockIdx.x;
    const float* xr = x + (size_t)t * D_DIM;
    float acc[E_NUM];
#pragma unroll
    for (int e = 0; e < E_NUM; e++) acc[e] = 0.f;
    for (int d = threadIdx.x; d < D_DIM; d += 256) {
        float xv = xr[d];
        const float* g = gw + d * E_NUM;
#pragma unroll
        for (int e = 0; e < E_NUM; e++) acc[e] = fmaf(xv, g[e], acc[e]);
    }
#pragma unroll
    for (int e = 0; e < E_NUM; e++)
        for (int off = 16; off > 0; off >>= 1)
            acc[e] += __shfl_down_sync(0xffffffffu, acc[e], off);
    __shared__ float wsum[8][E_NUM];
    int warp = threadIdx.x >> 5, lane = threadIdx.x & 31;
    if (lane == 0)
#pragma unroll
        for (int e = 0; e < E_NUM; e++) wsum[warp][e] = acc[e];
    __syncthreads();
    if (threadIdx.x == 0) {
        float logit[E_NUM];
        for (int e = 0; e < E_NUM; e++) {
            float s = 0.f;
            for (int w = 0; w < 8; w++) s += wsum[w][e];
            logit[e] = s;
        }
        float m = logit[0];
        for (int e = 1; e < E_NUM; e++) m = fmaxf(m, logit[e]);
        float p[E_NUM], sum = 0.f;
        for (int e = 0; e < E_NUM; e++) { p[e] = expf(logit[e] - m); sum += p[e]; }
        float inv = 1.f / sum;
        for (int e = 0; e < E_NUM; e++) { p[e] *= inv; g_probs[t * E_NUM + e] = p[e]; }
        int i0 = 0;
        for (int e = 1; e < E_NUM; e++) if (p[e] > p[i0]) i0 = e;
        int i1 = (i0 == 0) ? 1 : 0;
        for (int e = 0; e < E_NUM; e++) if (e != i0 && p[e] > p[i1]) i1 = e;
        float wn = p[i0] + p[i1];
        g_topk_idx[t * 2 + 0] = i0;
        g_topk_idx[t * 2 + 1] = i1;
        g_topk_w[t * 2 + 0] = p[i0] / wn;
        g_topk_w[t * 2 + 1] = p[i1] / wn;
        atomicAdd(&g_counts[i0], 1);
        atomicAdd(&g_counts[i1], 1);
    }
}

__global__ void offsets_kernel() {
    if (threadIdx.x == 0) {
        int o = 0, mt = 0;
        g_mtile_prefix[0] = 0;
        for (int e = 0; e < E_NUM; e++) {
            g_offsets[e] = o;
            o += g_counts[e];
            mt += (g_counts[e] + BM - 1) / BM;
            g_mtile_prefix[e + 1] = mt;
            g_cursor[e] = 0;
        }
        g_offsets[E_NUM] = o;
    }
}

__global__ void scatter_pos_kernel() {
    int idx = blockIdx.x * 256 + threadIdx.x;
    if (idx >= NSLOT) return;
    int e = g_topk_idx[idx];
    int pos = g_offsets[e] + atomicAdd(&g_cursor[e], 1);
    g_slot_token[pos] = idx >> 1;
    g_slot_w[pos]     = g_topk_w[idx];
    g_slot_of[idx]    = pos;
}

// =====================================================================
// SMEM layout (fp16): each tile row = 16 halves = 8 packed half2 words.
// Pair p (k=2p,2p+1) stored at word SIG(p). A thread (c=lane&3) reads one
// uint2 at word 2c -> pairs c (k=2c,2c+1) and c+4 (k=2c+8,2c+9): exactly
// the m16n8k16 fragment registers (a0,a2) / (b0,b1). Conflict-free LDS.64.
// =====================================================================

// ================= FFN1: H = silu(X Wg) * (X Wu) =================
__global__ __launch_bounds__(128, 2)
void ffn1_kernel(const float* __restrict__ x,
                 const float* __restrict__ Wg,
                 const float* __restrict__ Wu) {
    __shared__ __align__(16) uint32_t As [2][BM * 8];
    __shared__ __align__(16) uint32_t Bgs[2][BN * 8];
    __shared__ __align__(16) uint32_t Bus[2][BN * 8];

    const int mb = blockIdx.x, nb = blockIdx.y;
    if (mb >= g_mtile_prefix[E_NUM]) return;
    int e = 0;
    while (mb >= g_mtile_prefix[e + 1]) e++;
    const int m0   = g_offsets[e] + (mb - g_mtile_prefix[e]) * BM;
    const int mmax = g_offsets[e + 1];

    const int tid = threadIdx.x, lane = tid & 31, wid = tid >> 5;
    const int wm = wid >> 1;            // m offset wm*64
    const int wn = wid & 1;             // n offset wn*32

    // staging thread mapping: q = k-quad (0..3), rbase = row (0..31)
    const int q = tid & 3;
    const int rbase = tid >> 2;
    const int s0 = SIG(2 * q), s1 = SIG(2 * q + 1);

    int  arow[4], atok[4];
    bool av[4];
#pragma unroll
    for (int rr = 0; rr < 4; rr++) {
        arow[rr] = rbase + 32 * rr;
        int gr = m0 + arow[rr];
        av[rr]   = gr < mmax;
        atok[rr] = av[rr] ? g_slot_token[gr] : 0;
    }
    const float* bgp = Wg + (size_t)e * D_DIM * I_DIM + (size_t)nb * BN;
    const float* bup = Wu + (size_t)e * D_DIM * I_DIM + (size_t)nb * BN;

    float accg[4][4][4], accu[4][4][4];
#pragma unroll
    for (int i = 0; i < 4; i++)
#pragma unroll
        for (int j = 0; j < 4; j++)
#pragma unroll
            for (int k = 0; k < 4; k++) { accg[i][j][k] = 0.f; accu[i][j][k] = 0.f; }

    uint32_t pA[4][2], pBg[2][2], pBu[2][2];

#define FFN1_PREFETCH(K0)                                                        \
    do {                                                                         \
        _Pragma("unroll")                                                        \
        for (int rr = 0; rr < 4; rr++) {                                         \
            float4 v = make_float4(0.f, 0.f, 0.f, 0.f);                          \
            if (av[rr])                                                          \
                v = *(const float4*)(x + (size_t)atok[rr] * D_DIM + (K0) + 4 * q); \
            pA[rr][0] = pack_half2(v.x, v.y);                                    \
            pA[rr][1] = pack_half2(v.z, v.w);                                    \
        }                                                                        \
        _Pragma("unroll")                                                        \
        for (int g = 0; g < 2; g++) {                                            \
            int n = rbase + 32 * g;                                              \
            const float* pg = bgp + (size_t)((K0) + 4 * q) * I_DIM + n;          \
            const float* pu = bup + (size_t)((K0) + 4 * q) * I_DIM + n;          \
            pBg[g][0] = pack_half2(pg[0], pg[(size_t)I_DIM]);                    \
            pBg[g][1] = pack_half2(pg[(size_t)2 * I_DIM], pg[(size_t)3 * I_DIM]);\
            pBu[g][0] = pack_half2(pu[0], pu[(size_t)I_DIM]);                    \
            pBu[g][1] = pack_half2(pu[(size_t)2 * I_DIM], pu[(size_t)3 * I_DIM]);\
        }                                                                        \
    } while (0)

#define FFN1_COMMIT(BUF)                                                         \
    do {                                                                         \
        _Pragma("unroll")                                                        \
        for (int rr = 0; rr < 4; rr++) {                                         \
            int ro = arow[rr] * 8;                                               \
            As[BUF][ro + s0] = pA[rr][0];                                        \
            As[BUF][ro + s1] = pA[rr][1];                                        \
        }                                                                        \
        _Pragma("unroll")                                                        \
        for (int g = 0; g < 2; g++) {                                            \
            int no = (rbase + 32 * g) * 8;                                       \
            Bgs[BUF][no + s0] = pBg[g][0];                                       \
            Bgs[BUF][no + s1] = pBg[g][1];                                       \
            Bus[BUF][no + s0] = pBu[g][0];                                       \
            Bus[BUF][no + s1] = pBu[g][1];                                       \
        }                                                                        \
    } while (0)

    FFN1_PREFETCH(0);
    FFN1_COMMIT(0);
    __syncthreads();

    const int c = lane & 3;
    const int lrow = lane >> 2;
    const int NC = D_DIM / BK;          // 64
    for (int kc = 0; kc < NC; kc++) {
        const int cur = kc & 1;
        if (kc + 1 < NC) FFN1_PREFETCH((kc + 1) * BK);

        uint2 alo[4], ahi[4], bg[4], bu[4];
#pragma unroll
        for (int mf = 0; mf < 4; mf++) {
            int r = wm * 64 + mf * 16 + lrow;
            alo[mf] = *(const uint2*)&As[cur][r * 8 + 2 * c];
            ahi[mf] = *(const uint2*)&As[cur][(r + 8) * 8 + 2 * c];
        }
#pragma unroll
        for (int nf = 0; nf < 4; nf++) {
            int n = wn * 32 + nf * 8 + lrow;
            bg[nf] = *(const uint2*)&Bgs[cur][n * 8 + 2 * c];
            bu[nf] = *(const uint2*)&Bus[cur][n * 8 + 2 * c];
        }
#pragma unroll
        for (int mf = 0; mf < 4; mf++)
#pragma unroll
            for (int nf = 0; nf < 4; nf++) {
                MMA_F16(accg[mf][nf], alo[mf].x, ahi[mf].x, alo[mf].y, ahi[mf].y,
                        bg[nf].x, bg[nf].y);
                MMA_F16(accu[mf][nf], alo[mf].x, ahi[mf].x, alo[mf].y, ahi[mf].y,
                        bu[nf].x, bu[nf].y);
            }

        if (kc + 1 < NC) FFN1_COMMIT(cur ^ 1);
        __syncthreads();
    }

    // epilogue: h = silu(g) * u  -> fp16 g_H
#pragma unroll
    for (int mf = 0; mf < 4; mf++) {
        int r0 = m0 + wm * 64 + mf * 16 + lrow;
        int r1 = r0 + 8;
#pragma unroll
        for (int nf = 0; nf < 4; nf++) {
            int col = nb * BN + wn * 32 + nf * 8 + c * 2;
            if (r0 < mmax) {
                float g0 = accg[mf][nf][0], g1 = accg[mf][nf][1];
                float ox = g0 / (1.f + expf(-g0)) * accu[mf][nf][0];
                float oy = g1 / (1.f + expf(-g1)) * accu[mf][nf][1];
                *(uint32_t*)(g_H + (size_t)r0 * I_DIM + col) = pack_half2(ox, oy);
            }
            if (r1 < mmax) {
                float g2 = accg[mf][nf][2], g3 = accg[mf][nf][3];
                float ox = g2 / (1.f + expf(-g2)) * accu[mf][nf][2];
                float oy = g3 / (1.f + expf(-g3)) * accu[mf][nf][3];
                *(uint32_t*)(g_H + (size_t)r1 * I_DIM + col) = pack_half2(ox, oy);
            }
        }
    }
}

// ================= FFN2: Y = (H Wd) * slot_w =================
__global__ __launch_bounds__(128, 2)
void ffn2_kernel(const float* __restrict__ Wd) {
    __shared__ __align__(16) uint32_t As[2][BM * 8];
    __shared__ __align__(16) uint32_t Bs[2][BN * 8];

    const int mb = blockIdx.x, nb = blockIdx.y;
    if (mb >= g_mtile_prefix[E_NUM]) return;
    int e = 0;
    while (mb >= g_mtile_prefix[e + 1]) e++;
    const int m0   = g_offsets[e] + (mb - g_mtile_prefix[e]) * BM;
    const int mmax = g_offsets[e + 1];

    const int tid = threadIdx.x, lane = tid & 31, wid = tid >> 5;
    const int wm = wid >> 1, wn = wid & 1;

    const int q = tid & 3;
    const int rbase = tid >> 2;
    const int s0 = SIG(2 * q), s1 = SIG(2 * q + 1);

    int  arow[4];
    bool av[4];
#pragma unroll
    for (int rr = 0; rr < 4; rr++) {
        arow[rr] = rbase + 32 * rr;
        av[rr]   = (m0 + arow[rr]) < mmax;
    }
    const float* bp = Wd + (size_t)e * I_DIM * D_DIM + (size_t)nb * BN;

    float acc[4][4][4];
#pragma unroll
    for (int i = 0; i < 4; i++)
#pragma unroll
        for (int j = 0; j < 4; j++)
#pragma unroll
            for (int k = 0; k < 4; k++) acc[i][j][k] = 0.f;

    uint2    pA[4];
    uint32_t pB[2][2];

#define FFN2_PREFETCH(K0)                                                        \
    do {                                                                         \
        _Pragma("unroll")                                                        \
        for (int rr = 0; rr < 4; rr++) {                                         \
            pA[rr] = make_uint2(0u, 0u);                                         \
            if (av[rr])                                                          \
                pA[rr] = *(const uint2*)(g_H +                                   \
                         (size_t)(m0 + arow[rr]) * I_DIM + (K0) + 4 * q);        \
        }                                                                        \
        _Pragma("unroll")                                                        \
        for (int g = 0; g < 2; g++) {                                            \
            int n = rbase + 32 * g;                                              \
            const float* p = bp + (size_t)((K0) + 4 * q) * D_DIM + n;            \
            pB[g][0] = pack_half2(p[0], p[(size_t)D_DIM]);                       \
            pB[g][1] = pack_half2(p[(size_t)2 * D_DIM], p[(size_t)3 * D_DIM]);   \
        }                                                                        \
    } while (0)

#define FFN2_COMMIT(BUF)                                                         \
    do {                                                                         \
        _Pragma("unroll")                                                        \
        for (int rr = 0; rr < 4; rr++) {                                         \
            int ro = arow[rr] * 8;                                               \
            As[BUF][ro + s0] = pA[rr].x;                                         \
            As[BUF][ro + s1] = pA[rr].y;                                         \
        }                                                                        \
        _Pragma("unroll")                                                        \
        for (int g = 0; g < 2; g++) {                                            \
            int no = (rbase + 32 * g) * 8;                                       \
            Bs[BUF][no + s0] = pB[g][0];                                         \
            Bs[BUF][no + s1] = pB[g][1];                                         \
        }                                                                        \
    } while (0)

    FFN2_PREFETCH(0);
    FFN2_COMMIT(0);
    __syncthreads();

    const int c = lane & 3;
    const int lrow = lane >> 2;
    const int NC = I_DIM / BK;          // 176
    for (int kc = 0; kc < NC; kc++) {
        const int cur = kc & 1;
        if (kc + 1 < NC) FFN2_PREFETCH((kc + 1) * BK);

        uint2 alo[4], ahi[4], b[4];
#pragma unroll
        for (int mf = 0; mf < 4; mf++) {
            int r = wm * 64 + mf * 16 + lrow;
            alo[mf] = *(const uint2*)&As[cur][r * 8 + 2 * c];
            ahi[mf] = *(const uint2*)&As[cur][(r + 8) * 8 + 2 * c];
        }
#pragma unroll
        for (int nf = 0; nf < 4; nf++) {
            int n = wn * 32 + nf * 8 + lrow;
            b[nf] = *(const uint2*)&Bs[cur][n * 8 + 2 * c];
        }
#pragma unroll
        for (int mf = 0; mf < 4; mf++)
#pragma unroll
            for (int nf = 0; nf < 4; nf++)
                MMA_F16(acc[mf][nf], alo[mf].x, ahi[mf].x, alo[mf].y, ahi[mf].y,
                        b[nf].x, b[nf].y);

        if (kc + 1 < NC) FFN2_COMMIT(cur ^ 1);
        __syncthreads();
    }

#pragma unroll
    for (int mf = 0; mf < 4; mf++) {
        int r0 = m0 + wm * 64 + mf * 16 + lrow;
        int r1 = r0 + 8;
        float w0 = (r0 < mmax) ? g_slot_w[r0] : 0.f;
        float w1 = (r1 < mmax) ? g_slot_w[r1] : 0.f;
#pragma unroll
        for (int nf = 0; nf < 4; nf++) {
            int col = nb * BN + wn * 32 + nf * 8 + c * 2;
            if (r0 < mmax)
                *(float2*)(g_Y + (size_t)r0 * D_DIM + col) =
                    make_float2(acc[mf][nf][0] * w0, acc[mf][nf][1] * w0);
            if (r1 < mmax)
                *(float2*)(g_Y + (size_t)r1 * D_DIM + col) =
                    make_float2(acc[mf][nf][2] * w1, acc[mf][nf][3] * w1);
        }
    }
}

// ================= combine + aux (unchanged) =================
__global__ void combine_kernel(float* __restrict__ out) {
    int t = blockIdx.x;
    int s0 = g_slot_of[t * 2 + 0];
    int s1 = g_slot_of[t * 2 + 1];
    const float4* y0 = (const float4*)(g_Y + (size_t)s0 * D_DIM);
    const float4* y1 = (const float4*)(g_Y + (size_t)s1 * D_DIM);
    float4 a = y0[threadIdx.x], b = y1[threadIdx.x];
    ((float4*)(out + (size_t)t * D_DIM))[threadIdx.x] =
        make_float4(a.x + b.x, a.y + b.y, a.z + b.z, a.w + b.w);
}

__global__ void aux_kernel(float* __restrict__ out, int out_size) {
    __shared__ float red[256];
    __shared__ float esum[E_NUM];
    float part[E_NUM];
#pragma unroll
    for (int e = 0; e < E_NUM; e++) part[e] = 0.f;
    for (int t = threadIdx.x; t < T_TOK; t += 256)
#pragma unroll
        for (int e = 0; e < E_NUM; e++) part[e] += g_probs[t * E_NUM + e];
    for (int e = 0; e < E_NUM; e++) {
        red[threadIdx.x] = part[e];
        __syncthreads();
        for (int off = 128; off > 0; off >>= 1) {
            if (threadIdx.x < off) red[threadIdx.x] += red[threadIdx.x + off];
            __syncthreads();
        }
        if (threadIdx.x == 0) esum[e] = red[0];
        __syncthreads();
    }
    if (threadIdx.x == 0) {
        float aux = 0.f;
        for (int e = 0; e < E_NUM; e++)
            aux += ((float)g_counts[e] / (float)T_TOK) * (esum[e] / (float)T_TOK);
        aux *= 0.01f * (float)E_NUM;
        if (out_size > T_TOK * D_DIM) out[(size_t)T_TOK * D_DIM] = aux;
    }
}

// ================= launch =================
extern "C" void kernel_launch(void* const* d_in, const int* in_sizes, int n_in,
                              void* d_out, int out_size) {
    const float* x      = (const float*)d_in[0];
    const float* gate_w = (const float*)d_in[1];
    const float* Wg     = (const float*)d_in[2];
    const float* Wu     = (const float*)d_in[3];
    const float* Wd     = (const float*)d_in[4];
    float* out = (float*)d_out;

    init_kernel<<<1, 32>>>();
    router_kernel<<<T_TOK, 256>>>(x, gate_w);
    offsets_kernel<<<1, 32>>>();
    scatter_pos_kernel<<<(NSLOT + 255) / 256, 256>>>();

    dim3 g1(MAX_MT, I_DIM / BN);   // 144 x 44
    ffn1_kernel<<<g1, 128>>>(x, Wg, Wu);
    dim3 g2(MAX_MT, D_DIM / BN);   // 144 x 16
    ffn2_kernel<<<g2, 128>>>(Wd);

    combine_kernel<<<T_TOK, 256>>>(out);
    aux_kernel<<<1, 256>>>(out, out_size);
}